// round 4
// baseline (speedup 1.0000x reference)
#include <cuda_runtime.h>

#define NNODE 8192
#define HDIM  64
#define NEDGE 262144
#define NSUB  128
#define KSUB  128
#define NNEG  4
#define NH    (NNODE*HDIM)

// output layout (tuple flattened in order)
#define O_ADJ ((size_t)4)
#define O_P1  ((size_t)4 + (size_t)NNODE*NNODE)
#define O_N1  (O_P1 + NNODE)
#define O_P2  (O_N1 + (size_t)NNEG*NNODE)
#define O_N2  (O_P2 + NNODE)

// scratch (no allocations allowed)
__device__ float g_fbuf[9*NH + NNODE];
__device__ int   g_ibuf[3*NNODE + NEDGE];

// ---------------- helpers ----------------
__device__ __forceinline__ float prelu_f(float x, float a){ return x >= 0.f ? x : a*x; }
__device__ __forceinline__ float sigm(float x){
    float e = __expf(-x);                 // x<<0 -> inf
    return __fdividef(1.f, 1.f + e);      // 1/inf -> 0 (fast-div huge-denominator behavior)
}
__device__ __forceinline__ float warp_red(float v){
#pragma unroll
    for (int o = 16; o; o >>= 1) v += __shfl_xor_sync(0xffffffffu, v, o);
    return v;
}
__device__ __forceinline__ unsigned long long dup2(float a){
    unsigned long long r; asm("mov.b64 %0, {%1, %1};" : "=l"(r) : "f"(a)); return r;
}
__device__ __forceinline__ unsigned long long pk2(float x, float y){
    unsigned long long r; asm("mov.b64 %0, {%1, %2};" : "=l"(r) : "f"(x), "f"(y)); return r;
}
__device__ __forceinline__ float2 upk2(unsigned long long v){
    float2 r; asm("mov.b64 {%0, %1}, %2;" : "=f"(r.x), "=f"(r.y) : "l"(v)); return r;
}
__device__ __forceinline__ void ffma2(unsigned long long &c, unsigned long long a, unsigned long long b){
    asm("fma.rn.f32x2 %0, %1, %2, %3;" : "=l"(c) : "l"(a), "l"(b), "l"(c));
}
__device__ __forceinline__ float blk_sum128(float v, float* red){
    int t = threadIdx.x;
    red[t] = v; __syncthreads();
#pragma unroll
    for (int o = 64; o > 0; o >>= 1){ if (t < o) red[t] += red[t + o]; __syncthreads(); }
    float r = red[0]; __syncthreads(); return r;
}
__device__ __forceinline__ float blk_max128(float v, float* red){
    int t = threadIdx.x;
    red[t] = v; __syncthreads();
#pragma unroll
    for (int o = 64; o > 0; o >>= 1){ if (t < o) red[t] = fmaxf(red[t], red[t + o]); __syncthreads(); }
    float r = red[0]; __syncthreads(); return r;
}

// ---------------- CSR build ----------------
__global__ void k_init(int* __restrict__ cnt, float* __restrict__ out){
    int i = blockIdx.x*blockDim.x + threadIdx.x;
    if (i < NNODE) cnt[i] = 0;
    if (i < 4) out[i] = 0.f;
}
__global__ void k_hist(const int* __restrict__ dst, int* __restrict__ cnt){
    int i = blockIdx.x*256 + threadIdx.x;
    if (i < NEDGE) atomicAdd(&cnt[dst[i]], 1);
}
__global__ void __launch_bounds__(1024) k_scan(const int* __restrict__ cnt,
                                               int* __restrict__ off, int* __restrict__ cur){
    __shared__ int sh[1024];
    int t = threadIdx.x;
    int base = t*8;
    int loc[8]; int run = 0;
#pragma unroll
    for (int i = 0; i < 8; i++){ loc[i] = run; run += cnt[base + i]; }
    sh[t] = run; __syncthreads();
    for (int d = 1; d < 1024; d <<= 1){
        int v = 0; if (t >= d) v = sh[t - d];
        __syncthreads();
        sh[t] += v;
        __syncthreads();
    }
    int excl = sh[t] - run;
#pragma unroll
    for (int i = 0; i < 8; i++){ int o = excl + loc[i]; off[base+i] = o; cur[base+i] = o; }
}
__global__ void k_scatter(const int* __restrict__ dst, int* __restrict__ cur, int* __restrict__ csr){
    int i = blockIdx.x*256 + threadIdx.x;
    if (i < NEDGE){
        int p = atomicAdd(&cur[dst[i]], 1);
        csr[p] = i;
    }
}

// ---------------- dense [N,64]@[64,64] (+optional bias/prelu) ----------------
__global__ void __launch_bounds__(256) k_gemm64(
    const float* __restrict__ X, const float* __restrict__ W,
    const float* __restrict__ bias, const float* __restrict__ slope,
    float* __restrict__ Y)
{
    __shared__ float4 Wsm[1024];
    __shared__ float  bsm[64];
    int t = threadIdx.x;
    const float4* W4 = (const float4*)W;
#pragma unroll
    for (int i = t; i < 1024; i += 256) Wsm[i] = W4[i];
    if (t < 64) bsm[t] = bias ? bias[t] : 0.f;
    __syncthreads();
    int row = blockIdx.x*256 + t;
    const float4* xr = (const float4*)(X + (size_t)row*64);
    float x[64];
#pragma unroll
    for (int i = 0; i < 16; i++){
        float4 v = xr[i];
        x[4*i]=v.x; x[4*i+1]=v.y; x[4*i+2]=v.z; x[4*i+3]=v.w;
    }
    bool act = (slope != nullptr);
    float sl = act ? *slope : 0.f;
    float4* yr = (float4*)(Y + (size_t)row*64);
    for (int c = 0; c < 16; c++){
        float4 acc = make_float4(0.f,0.f,0.f,0.f);
#pragma unroll
        for (int k = 0; k < 64; k++){
            float4 w = Wsm[k*16 + c];
            acc.x = fmaf(x[k], w.x, acc.x);
            acc.y = fmaf(x[k], w.y, acc.y);
            acc.z = fmaf(x[k], w.z, acc.z);
            acc.w = fmaf(x[k], w.w, acc.w);
        }
        acc.x += bsm[4*c]; acc.y += bsm[4*c+1]; acc.z += bsm[4*c+2]; acc.w += bsm[4*c+3];
        if (act){
            acc.x = prelu_f(acc.x, sl); acc.y = prelu_f(acc.y, sl);
            acc.z = prelu_f(acc.z, sl); acc.w = prelu_f(acc.w, sl);
        }
        yr[c] = acc;
    }
}

// ---------------- sparse aggregations (CSR gather, 64 threads/node) ----------------
__global__ void __launch_bounds__(256) k_agg1(
    const int* __restrict__ src, const float* __restrict__ ew, const float* __restrict__ aw,
    const int* __restrict__ off, const int* __restrict__ cnt, const int* __restrict__ csr,
    const float* __restrict__ h1, const float* __restrict__ b1, const float* __restrict__ a1p,
    float* __restrict__ v1, float* __restrict__ nbr)
{
    int t = threadIdx.x; int f = t & 63; int g = t >> 6;
    int n = blockIdx.x*4 + g;
    int o = off[n], c = cnt[n];
    float acc = 0.f, acc2 = 0.f;
    for (int i = 0; i < c; i++){
        int e = csr[o + i];
        int s = src[e];
        float v = h1[(size_t)s*64 + f];
        acc  = fmaf(ew[e], v, acc);
        acc2 = fmaf(aw[e], v, acc2);
    }
    float z = acc + b1[f];
    v1[(size_t)n*64 + f]  = prelu_f(z, *a1p);
    nbr[(size_t)n*64 + f] = acc2;
}
__global__ void __launch_bounds__(256) k_agg2(
    const int* __restrict__ src, const float* __restrict__ ew,
    const int* __restrict__ off, const int* __restrict__ cnt, const int* __restrict__ csr,
    const float* __restrict__ h2, const float* __restrict__ b2, const float* __restrict__ a2p,
    float* __restrict__ v2)
{
    int t = threadIdx.x; int f = t & 63; int g = t >> 6;
    int n = blockIdx.x*4 + g;
    int o = off[n], c = cnt[n];
    float acc = 0.f;
    for (int i = 0; i < c; i++){
        int e = csr[o + i];
        int s = src[e];
        acc = fmaf(ew[e], h2[(size_t)s*64 + f], acc);
    }
    float z = acc + b2[f];
    v2[(size_t)n*64 + f] = prelu_f(z, *a2p);
}

// ---------------- transpose nv -> nvT [64][8192] ----------------
__global__ void k_trans(const float* __restrict__ nv, float* __restrict__ nvT){
    __shared__ float tile[32][33];
    int bi = blockIdx.x*32;   // row base (node)
    int bj = blockIdx.y*32;   // col base (feature)
    int tx = threadIdx.x, ty = threadIdx.y;
#pragma unroll
    for (int j = 0; j < 32; j += 8)
        tile[ty + j][tx] = nv[(size_t)(bi + ty + j)*64 + bj + tx];
    __syncthreads();
#pragma unroll
    for (int j = 0; j < 32; j += 8)
        nvT[(size_t)(bj + ty + j)*NNODE + bi + tx] = tile[tx][ty + j];
}

// ---------------- discriminators + score (1 warp / node) ----------------
__global__ void __launch_bounds__(256) k_disc(
    const float* __restrict__ t1, const float* __restrict__ t2,
    const float* __restrict__ nv, const float* __restrict__ nbr,
    const int* __restrict__ neg1, const int* __restrict__ neg2,
    const float* __restrict__ Ws, const float* __restrict__ bs,
    const float* __restrict__ bd1p, const float* __restrict__ bd2p,
    float* __restrict__ score, float* __restrict__ out)
{
    int tid = blockIdx.x*256 + threadIdx.x;
    int n = tid >> 5; int l = tid & 31;
    float nv0 = nv[(size_t)n*64 + l],  nv1 = nv[(size_t)n*64 + 32 + l];
    float nb0 = nbr[(size_t)n*64 + l], nb1 = nbr[(size_t)n*64 + 32 + l];
    float bd1 = *bd1p, bd2 = *bd2p;

    float d = warp_red(t1[(size_t)n*64 + l]*nv0 + t1[(size_t)n*64 + 32 + l]*nv1);
    if (l == 0) out[O_P1 + n] = d + bd1;
#pragma unroll
    for (int k = 0; k < NNEG; k++){
        int m = neg1[k*NNODE + n];
        float dk = warp_red(t1[(size_t)m*64 + l]*nv0 + t1[(size_t)m*64 + 32 + l]*nv1);
        if (l == 0) out[O_N1 + (size_t)k*NNODE + n] = dk + bd1;
    }
    float d2 = warp_red(t2[(size_t)n*64 + l]*nb0 + t2[(size_t)n*64 + 32 + l]*nb1);
    if (l == 0) out[O_P2 + n] = d2 + bd2;
#pragma unroll
    for (int k = 0; k < NNEG; k++){
        int m = neg2[k*NNODE + n];
        float dk = warp_red(t2[(size_t)m*64 + l]*nb0 + t2[(size_t)m*64 + 32 + l]*nb1);
        if (l == 0) out[O_N2 + (size_t)k*NNODE + n] = dk + bd2;
    }
    float sc = warp_red(Ws[l]*nv0 + Ws[32 + l]*nv1) + bs[0];
    if (l == 0) score[n] = sigm(sc);
}

// ---------------- subgraph losses (1 block / subgraph; sorts -> reductions) ----------------
__global__ void __launch_bounds__(128) k_subg(
    const int* __restrict__ aidx, const int* __restrict__ nidx,
    const float* __restrict__ alap, const float* __restrict__ nlap,
    const float* __restrict__ score, float* __restrict__ out)
{
    __shared__ float sa[128], sn[128], red[128];
    int s = blockIdx.x, t = threadIdx.x;
    sa[t] = score[aidx[s*KSUB + t]];
    sn[t] = score[nidx[s*KSUB + t]];
    __syncthreads();
    const float* la = alap + ((size_t)s*KSUB + t)*KSUB;
    const float* ln = nlap + ((size_t)s*KSUB + t)*KSUB;
    float ra = 0.f, rn = 0.f;
#pragma unroll 4
    for (int j = 0; j < KSUB; j++){
        ra = fmaf(la[j], sa[j], ra);
        rn = fmaf(ln[j], sn[j], rn);
    }
    float myA = sa[t], myN = sn[t];
    float hc = myA*ra + myN*rn;

    float suma = blk_sum128(myA, red);
    float amax = blk_max128(myA, red);
    float nmax = blk_max128(myN, red);
    float mean = suma * (1.f/128.f);
    float bv = (myA < mean) ? myA : -1e30f;     // largest value strictly below mean
    float below = blk_max128(bv, red);
    float abm = (below > -1e29f) ? below : amax; // argmax over all-false -> index 0 -> max
    float hom = blk_sum128(hc, red);

    if (t == 0){
        atomicAdd(out + 0, fmaxf(0.f, 1.f - amax + nmax) * (1.f/128.f)); // ranking_loss
        atomicAdd(out + 1, fmaxf(0.f, 1.f - amax + abm)  * (1.f/128.f)); // ranking_inner_loss
        atomicAdd(out + 2, suma * (1.f/128.f));                          // sp_loss
        atomicAdd(out + 3, hom  * (1.f/256.f));                          // hom_loss
    }
}

// ---------------- adj = sigmoid(nv @ nv^T): fp32 via packed f32x2 FMA ----------------
#define TS 132   // padded k-major smem row stride (floats), 16B-aligned
__global__ void __launch_bounds__(256) k_adj(const float* __restrict__ nvT, float* __restrict__ out)
{
    extern __shared__ float sm[];
    float* As = sm;            // [64][TS]
    float* Bs = sm + 64*TS;    // [64][TS]
    int t = threadIdx.x;
    int bx = blockIdx.x, by = blockIdx.y;

    const float4* T4 = (const float4*)nvT;   // [64][2048 float4]
#pragma unroll
    for (int p = 0; p < 8; p++){
        int q = t + p*256;
        int k = q >> 5, c4 = q & 31;
        ((float4*)(As + k*TS))[c4] = T4[(size_t)k*2048 + by*32 + c4];
        ((float4*)(Bs + k*TS))[c4] = T4[(size_t)k*2048 + bx*32 + c4];
    }
    __syncthreads();

    int tx = t & 15, ty = t >> 4;
    unsigned long long acc[8][4];
#pragma unroll
    for (int i = 0; i < 8; i++)
#pragma unroll
        for (int j = 0; j < 4; j++) acc[i][j] = 0ULL;

#pragma unroll 8
    for (int k = 0; k < 64; k++){
        const float4* ar = (const float4*)(As + k*TS + ty*8);
        const float4* br = (const float4*)(Bs + k*TS + tx*8);
        float4 a0 = ar[0], a1 = ar[1];
        float4 b0 = br[0], b1 = br[1];
        unsigned long long bp0 = pk2(b0.x, b0.y), bp1 = pk2(b0.z, b0.w);
        unsigned long long bp2 = pk2(b1.x, b1.y), bp3 = pk2(b1.z, b1.w);
        float av[8] = {a0.x, a0.y, a0.z, a0.w, a1.x, a1.y, a1.z, a1.w};
#pragma unroll
        for (int i = 0; i < 8; i++){
            unsigned long long ad = dup2(av[i]);
            ffma2(acc[i][0], ad, bp0);
            ffma2(acc[i][1], ad, bp1);
            ffma2(acc[i][2], ad, bp2);
            ffma2(acc[i][3], ad, bp3);
        }
    }

    int gr0 = by*128 + ty*8;
    int gc0 = bx*128 + tx*8;
#pragma unroll
    for (int i = 0; i < 8; i++){
        float2 c01 = upk2(acc[i][0]);
        float2 c23 = upk2(acc[i][1]);
        float2 c45 = upk2(acc[i][2]);
        float2 c67 = upk2(acc[i][3]);
        float4 o0 = make_float4(sigm(c01.x), sigm(c01.y), sigm(c23.x), sigm(c23.y));
        float4 o1 = make_float4(sigm(c45.x), sigm(c45.y), sigm(c67.x), sigm(c67.y));
        float4* dstp = (float4*)(out + O_ADJ + (size_t)(gr0 + i)*NNODE + gc0);
        dstp[0] = o0; dstp[1] = o1;
    }
}

// ---------------- host ----------------
extern "C" void kernel_launch(void* const* d_in, const int* in_sizes, int n_in,
                              void* d_out, int out_size)
{
    const float* feat = (const float*)d_in[0];
    const int*   esrc = (const int*)  d_in[1];
    const int*   edst = (const int*)  d_in[2];
    const float* ew   = (const float*)d_in[3];
    const float* aw   = (const float*)d_in[4];
    const int*   neg1 = (const int*)  d_in[5];
    const int*   neg2 = (const int*)  d_in[6];
    const int*   aidx = (const int*)  d_in[7];
    const int*   nidx = (const int*)  d_in[8];
    const float* alap = (const float*)d_in[9];
    const float* nlap = (const float*)d_in[10];
    const float* W1   = (const float*)d_in[11];
    const float* b1   = (const float*)d_in[12];
    const float* W2   = (const float*)d_in[13];
    const float* b2   = (const float*)d_in[14];
    const float* Wq   = (const float*)d_in[15];
    const float* bq   = (const float*)d_in[16];
    const float* Ws   = (const float*)d_in[17];
    const float* bs   = (const float*)d_in[18];
    const float* B1   = (const float*)d_in[19];
    const float* bd1  = (const float*)d_in[20];
    const float* B2   = (const float*)d_in[21];
    const float* bd2  = (const float*)d_in[22];
    const float* a1   = (const float*)d_in[23];
    const float* a2   = (const float*)d_in[24];
    const float* aq   = (const float*)d_in[25];
    float* out = (float*)d_out;

    float* fb = nullptr; int* ib = nullptr;
    cudaGetSymbolAddress((void**)&fb, g_fbuf);
    cudaGetSymbolAddress((void**)&ib, g_ibuf);
    float* h1    = fb + 0*NH;
    float* v1    = fb + 1*NH;
    float* h2    = fb + 2*NH;
    float* v2    = fb + 3*NH;
    float* nv    = fb + 4*NH;
    float* nvT   = fb + 5*NH;
    float* nbr   = fb + 6*NH;
    float* t1    = fb + 7*NH;
    float* t2    = fb + 8*NH;
    float* score = fb + 9*NH;
    int* cnt = ib;
    int* off = ib + NNODE;
    int* cur = ib + 2*NNODE;
    int* csr = ib + 3*NNODE;

    const int smem_adj = 2*64*TS*4;
    cudaFuncSetAttribute(k_adj, cudaFuncAttributeMaxDynamicSharedMemorySize, smem_adj);

    // CSR build + zero accumulators
    k_init<<<32, 256>>>(cnt, out);
    k_hist<<<NEDGE/256, 256>>>(edst, cnt);
    k_scan<<<1, 1024>>>(cnt, off, cur);
    k_scatter<<<NEDGE/256, 256>>>(edst, cur, csr);

    // GCN pipeline
    k_gemm64<<<32, 256>>>(feat, W1, nullptr, nullptr, h1);                       // node_transemb
    k_agg1<<<NNODE/4, 256>>>(esrc, ew, aw, off, cnt, csr, h1, b1, a1, v1, nbr);  // v1 + node_neighbor
    k_gemm64<<<32, 256>>>(v1, W2, nullptr, nullptr, h2);
    k_agg2<<<NNODE/4, 256>>>(esrc, ew, off, cnt, csr, h2, b2, a2, v2);
    k_gemm64<<<32, 256>>>(v2, Wq, bq, aq, nv);                                   // node_vec
    k_gemm64<<<32, 256>>>(feat, B1, nullptr, nullptr, t1);                       // feat@B1
    k_gemm64<<<32, 256>>>(nv, B2, nullptr, nullptr, t2);                         // nv@B2
    k_trans<<<dim3(NNODE/32, HDIM/32), dim3(32, 8)>>>(nv, nvT);

    // Discriminators + MIL scores
    k_disc<<<NNODE*32/256, 256>>>(t1, t2, nv, nbr, neg1, neg2, Ws, bs, bd1, bd2, score, out);

    // Subgraph losses
    k_subg<<<NSUB, 128>>>(aidx, nidx, alap, nlap, score, out);

    // adj_rebuilt (dominant cost)
    k_adj<<<dim3(NNODE/128, NNODE/128), 256, smem_adj>>>(nvT, out);

    (void)in_sizes; (void)n_in; (void)out_size;
}

// round 7
// speedup vs baseline: 1.2050x; 1.2050x over previous
#include <cuda_runtime.h>
#include <cuda_bf16.h>
#include <cstdint>

#define NNODE 8192
#define HDIM  64
#define NEDGE 262144
#define NSUB  128
#define KSUB  128
#define NNEG  4
#define NH    (NNODE*HDIM)

// output layout (tuple flattened in order)
#define O_ADJ ((size_t)4)
#define O_P1  ((size_t)4 + (size_t)NNODE*NNODE)
#define O_N1  (O_P1 + NNODE)
#define O_P2  (O_N1 + (size_t)NNEG*NNODE)
#define O_N2  (O_P2 + NNODE)

// scratch (no allocations allowed)
__device__ float          g_fbuf[9*NH + NNODE];
__device__ int            g_ibuf[3*NNODE + NEDGE];
__device__ __nv_bfloat16  g_split[3*NH];           // hi / mid / lo planes of node_vec

// ---------------- helpers ----------------
__device__ __forceinline__ float prelu_f(float x, float a){ return x >= 0.f ? x : a*x; }
__device__ __forceinline__ float sigm(float x){
    float e = __expf(-x);
    return __fdividef(1.f, 1.f + e);
}
__device__ __forceinline__ float warp_red(float v){
#pragma unroll
    for (int o = 16; o; o >>= 1) v += __shfl_xor_sync(0xffffffffu, v, o);
    return v;
}
__device__ __forceinline__ float blk_sum128(float v, float* red){
    int t = threadIdx.x;
    red[t] = v; __syncthreads();
#pragma unroll
    for (int o = 64; o > 0; o >>= 1){ if (t < o) red[t] += red[t + o]; __syncthreads(); }
    float r = red[0]; __syncthreads(); return r;
}
__device__ __forceinline__ float blk_max128(float v, float* red){
    int t = threadIdx.x;
    red[t] = v; __syncthreads();
#pragma unroll
    for (int o = 64; o > 0; o >>= 1){ if (t < o) red[t] = fmaxf(red[t], red[t + o]); __syncthreads(); }
    float r = red[0]; __syncthreads(); return r;
}
__device__ __forceinline__ uint32_t smem_u32(const void* p){
    uint32_t a;
    asm("{ .reg .u64 t; cvta.to.shared.u64 t, %1; cvt.u32.u64 %0, t; }" : "=r"(a) : "l"(p));
    return a;
}
__device__ __forceinline__ void ldm_x4(uint32_t* r, uint32_t addr){
    asm volatile("ldmatrix.sync.aligned.m8n8.x4.shared.b16 {%0,%1,%2,%3}, [%4];"
                 : "=r"(r[0]), "=r"(r[1]), "=r"(r[2]), "=r"(r[3]) : "r"(addr));
}
__device__ __forceinline__ void mma_bf16(float* c, const uint32_t* a, uint32_t b0, uint32_t b1){
    asm volatile(
        "mma.sync.aligned.m16n8k16.row.col.f32.bf16.bf16.f32 "
        "{%0,%1,%2,%3}, {%4,%5,%6,%7}, {%8,%9}, {%0,%1,%2,%3};"
        : "+f"(c[0]), "+f"(c[1]), "+f"(c[2]), "+f"(c[3])
        : "r"(a[0]), "r"(a[1]), "r"(a[2]), "r"(a[3]), "r"(b0), "r"(b1));
}

// ---------------- CSR build ----------------
__global__ void k_init(int* __restrict__ cnt, float* __restrict__ out){
    int i = blockIdx.x*blockDim.x + threadIdx.x;
    if (i < NNODE) cnt[i] = 0;
    if (i < 4) out[i] = 0.f;
}
__global__ void k_hist(const int* __restrict__ dst, int* __restrict__ cnt){
    int i = blockIdx.x*256 + threadIdx.x;
    if (i < NEDGE) atomicAdd(&cnt[dst[i]], 1);
}
__global__ void __launch_bounds__(1024) k_scan(const int* __restrict__ cnt,
                                               int* __restrict__ off, int* __restrict__ cur){
    __shared__ int sh[1024];
    int t = threadIdx.x;
    int base = t*8;
    int loc[8]; int run = 0;
#pragma unroll
    for (int i = 0; i < 8; i++){ loc[i] = run; run += cnt[base + i]; }
    sh[t] = run; __syncthreads();
    for (int d = 1; d < 1024; d <<= 1){
        int v = 0; if (t >= d) v = sh[t - d];
        __syncthreads();
        sh[t] += v;
        __syncthreads();
    }
    int excl = sh[t] - run;
#pragma unroll
    for (int i = 0; i < 8; i++){ int o = excl + loc[i]; off[base+i] = o; cur[base+i] = o; }
}
__global__ void k_scatter(const int* __restrict__ dst, int* __restrict__ cur, int* __restrict__ csr){
    int i = blockIdx.x*256 + threadIdx.x;
    if (i < NEDGE){
        int p = atomicAdd(&cur[dst[i]], 1);
        csr[p] = i;
    }
}

// ---------------- dense [N,64]@[64,64] (+optional bias/prelu), 128 CTAs ----------------
__global__ void __launch_bounds__(256) k_gemm64(
    const float* __restrict__ X, const float* __restrict__ W,
    const float* __restrict__ bias, const float* __restrict__ slope,
    float* __restrict__ Y)
{
    __shared__ float4 Wsm[1024];
    __shared__ float  bsm[64];
    int t = threadIdx.x;
    const float4* W4 = (const float4*)W;
#pragma unroll
    for (int i = t; i < 1024; i += 256) Wsm[i] = W4[i];
    if (t < 64) bsm[t] = bias ? bias[t] : 0.f;
    __syncthreads();
    int row  = blockIdx.x*64 + (t & 63);
    int part = t >> 6;
    const float4* xr = (const float4*)(X + (size_t)row*64);
    float x[64];
#pragma unroll
    for (int i = 0; i < 16; i++){
        float4 v = xr[i];
        x[4*i]=v.x; x[4*i+1]=v.y; x[4*i+2]=v.z; x[4*i+3]=v.w;
    }
    bool act = (slope != nullptr);
    float sl = act ? *slope : 0.f;
    float4* yr = (float4*)(Y + (size_t)row*64);
#pragma unroll
    for (int cc = 0; cc < 4; cc++){
        int c4 = part*4 + cc;
        float4 acc = make_float4(0.f,0.f,0.f,0.f);
#pragma unroll
        for (int k = 0; k < 64; k++){
            float4 w = Wsm[k*16 + c4];
            acc.x = fmaf(x[k], w.x, acc.x);
            acc.y = fmaf(x[k], w.y, acc.y);
            acc.z = fmaf(x[k], w.z, acc.z);
            acc.w = fmaf(x[k], w.w, acc.w);
        }
        acc.x += bsm[4*c4]; acc.y += bsm[4*c4+1]; acc.z += bsm[4*c4+2]; acc.w += bsm[4*c4+3];
        if (act){
            acc.x = prelu_f(acc.x, sl); acc.y = prelu_f(acc.y, sl);
            acc.z = prelu_f(acc.z, sl); acc.w = prelu_f(acc.w, sl);
        }
        yr[c4] = acc;
    }
}

// ---------------- sparse aggregations (CSR gather, 64 threads/node) ----------------
__global__ void __launch_bounds__(256) k_agg1(
    const int* __restrict__ src, const float* __restrict__ ew, const float* __restrict__ aw,
    const int* __restrict__ off, const int* __restrict__ cnt, const int* __restrict__ csr,
    const float* __restrict__ h1, const float* __restrict__ b1, const float* __restrict__ a1p,
    float* __restrict__ v1, float* __restrict__ nbr)
{
    int t = threadIdx.x; int f = t & 63; int g = t >> 6;
    int n = blockIdx.x*4 + g;
    int o = off[n], c = cnt[n];
    float acc = 0.f, acc2 = 0.f;
    for (int i = 0; i < c; i++){
        int e = csr[o + i];
        int s = src[e];
        float v = h1[(size_t)s*64 + f];
        acc  = fmaf(ew[e], v, acc);
        acc2 = fmaf(aw[e], v, acc2);
    }
    float z = acc + b1[f];
    v1[(size_t)n*64 + f]  = prelu_f(z, *a1p);
    nbr[(size_t)n*64 + f] = acc2;
}
__global__ void __launch_bounds__(256) k_agg2(
    const int* __restrict__ src, const float* __restrict__ ew,
    const int* __restrict__ off, const int* __restrict__ cnt, const int* __restrict__ csr,
    const float* __restrict__ h2, const float* __restrict__ b2, const float* __restrict__ a2p,
    float* __restrict__ v2)
{
    int t = threadIdx.x; int f = t & 63; int g = t >> 6;
    int n = blockIdx.x*4 + g;
    int o = off[n], c = cnt[n];
    float acc = 0.f;
    for (int i = 0; i < c; i++){
        int e = csr[o + i];
        int s = src[e];
        acc = fmaf(ew[e], h2[(size_t)s*64 + f], acc);
    }
    float z = acc + b2[f];
    v2[(size_t)n*64 + f] = prelu_f(z, *a2p);
}

// ---------------- split nv into 3 bf16 planes (hi/mid/lo) ----------------
__global__ void k_split(const float* __restrict__ nv, __nv_bfloat16* __restrict__ sp){
    int i = blockIdx.x*256 + threadIdx.x;
    float a = nv[i];
    __nv_bfloat16 h = __float2bfloat16(a);
    float r1 = a - __bfloat162float(h);
    __nv_bfloat16 m = __float2bfloat16(r1);
    float r2 = r1 - __bfloat162float(m);
    __nv_bfloat16 l = __float2bfloat16(r2);
    sp[i] = h; sp[NH + i] = m; sp[2*NH + i] = l;
}

// ---------------- discriminators + score (1 warp / node) ----------------
__global__ void __launch_bounds__(256) k_disc(
    const float* __restrict__ t1, const float* __restrict__ t2,
    const float* __restrict__ nv, const float* __restrict__ nbr,
    const int* __restrict__ neg1, const int* __restrict__ neg2,
    const float* __restrict__ Ws, const float* __restrict__ bs,
    const float* __restrict__ bd1p, const float* __restrict__ bd2p,
    float* __restrict__ score, float* __restrict__ out)
{
    int tid = blockIdx.x*256 + threadIdx.x;
    int n = tid >> 5; int l = tid & 31;
    float nv0 = nv[(size_t)n*64 + l],  nv1 = nv[(size_t)n*64 + 32 + l];
    float nb0 = nbr[(size_t)n*64 + l], nb1 = nbr[(size_t)n*64 + 32 + l];
    float bd1 = *bd1p, bd2 = *bd2p;

    float d = warp_red(t1[(size_t)n*64 + l]*nv0 + t1[(size_t)n*64 + 32 + l]*nv1);
    if (l == 0) out[O_P1 + n] = d + bd1;
#pragma unroll
    for (int k = 0; k < NNEG; k++){
        int m = neg1[k*NNODE + n];
        float dk = warp_red(t1[(size_t)m*64 + l]*nv0 + t1[(size_t)m*64 + 32 + l]*nv1);
        if (l == 0) out[O_N1 + (size_t)k*NNODE + n] = dk + bd1;
    }
    float d2 = warp_red(t2[(size_t)n*64 + l]*nb0 + t2[(size_t)n*64 + 32 + l]*nb1);
    if (l == 0) out[O_P2 + n] = d2 + bd2;
#pragma unroll
    for (int k = 0; k < NNEG; k++){
        int m = neg2[k*NNODE + n];
        float dk = warp_red(t2[(size_t)m*64 + l]*nb0 + t2[(size_t)m*64 + 32 + l]*nb1);
        if (l == 0) out[O_N2 + (size_t)k*NNODE + n] = dk + bd2;
    }
    float sc = warp_red(Ws[l]*nv0 + Ws[32 + l]*nv1) + bs[0];
    if (l == 0) score[n] = sigm(sc);
}

// ---------------- subgraph losses ----------------
__global__ void __launch_bounds__(128) k_subg(
    const int* __restrict__ aidx, const int* __restrict__ nidx,
    const float* __restrict__ alap, const float* __restrict__ nlap,
    const float* __restrict__ score, float* __restrict__ out)
{
    __shared__ float sa[128], sn[128], red[128];
    int s = blockIdx.x, t = threadIdx.x;
    sa[t] = score[aidx[s*KSUB + t]];
    sn[t] = score[nidx[s*KSUB + t]];
    __syncthreads();
    const float* la = alap + ((size_t)s*KSUB + t)*KSUB;
    const float* ln = nlap + ((size_t)s*KSUB + t)*KSUB;
    float ra = 0.f, rn = 0.f;
#pragma unroll 4
    for (int j = 0; j < KSUB; j++){
        ra = fmaf(la[j], sa[j], ra);
        rn = fmaf(ln[j], sn[j], rn);
    }
    float myA = sa[t], myN = sn[t];
    float hc = myA*ra + myN*rn;

    float suma = blk_sum128(myA, red);
    float amax = blk_max128(myA, red);
    float nmax = blk_max128(myN, red);
    float mean = suma * (1.f/128.f);
    float bv = (myA < mean) ? myA : -1e30f;
    float below = blk_max128(bv, red);
    float abm = (below > -1e29f) ? below : amax;
    float hom = blk_sum128(hc, red);

    if (t == 0){
        atomicAdd(out + 0, fmaxf(0.f, 1.f - amax + nmax) * (1.f/128.f));
        atomicAdd(out + 1, fmaxf(0.f, 1.f - amax + abm)  * (1.f/128.f));
        atomicAdd(out + 2, suma * (1.f/128.f));
        atomicAdd(out + 3, hom  * (1.f/256.f));
    }
}

// ---------------- adj = sigmoid(nv @ nv^T) via mma.sync bf16, 3-way split, symmetric ----------------
// 2080 triangular 128x128 tiles. Operand tiles: [128 rows][64 k] bf16, row stride
// padded to 144B (72 bf16) -> 16B-aligned rows, conflict-free ldmatrix.
#define ADJ_NT 2080
#define TPAD   72
#define TILEB  (128*TPAD*2)       // 18432 B
#define SMA_SMEM (6*TILEB)        // 110592 B; epilogue stage [128][129] f32 reuses this

__global__ void __launch_bounds__(256, 2) k_adj_mma(const __nv_bfloat16* __restrict__ sp,
                                                    float* __restrict__ out)
{
    extern __shared__ char smem[];
    uint32_t sb = smem_u32(smem);
    int t = threadIdx.x, wid = t >> 5, lid = t & 31;

    // triangular decode: i -> (by, bx) with bx <= by
    int i = blockIdx.x;
    int by = (int)((sqrtf(8.f*(float)i + 1.f) - 1.f) * 0.5f);
    while ((by+1)*(by+2)/2 <= i) by++;
    while (by*(by+1)/2 > i) by--;
    int bx = i - by*(by+1)/2;

    // load 6 operand tiles (A hi/mid/lo rows from by, B hi/mid/lo rows from bx)
    const uint4* g = (const uint4*)sp;          // per split: 65536 uint4; node row = 8 uint4
    for (int q = t; q < 6144; q += 256){
        int tile = q >> 10;
        int idx  = q & 1023;
        int r = idx >> 3, c = idx & 7;
        int s2   = (tile < 3) ? tile : tile - 3;
        int node = ((tile < 3) ? by : bx)*128 + r;
        uint4 v = g[s2*65536 + node*8 + c];
        *(uint4*)(smem + tile*TILEB + r*144 + c*16) = v;
    }
    __syncthreads();

    // warp tiling: 2 row-warps x 4 col-warps; each warp: 64 rows x 32 cols
    int wr = wid & 1, wc = wid >> 1;
    int arow  = lid & 15;
    int akoff = (lid >> 4) * 8;
    int bnode = (lid & 7) | ((lid >> 4) << 3);
    int bkoff = ((lid >> 3) & 1) * 8;

    float acc[4][4][4];
#pragma unroll
    for (int mi = 0; mi < 4; mi++)
#pragma unroll
        for (int ni = 0; ni < 4; ni++)
#pragma unroll
            for (int j = 0; j < 4; j++) acc[mi][ni][j] = 0.f;

    const int ca[6] = {0,0,1,0,2,1};
    const int cb[6] = {0,1,0,2,0,1};
#pragma unroll
    for (int cm = 0; cm < 6; cm++){
        uint32_t aT = sb + ca[cm]*TILEB;
        uint32_t bT = sb + (3 + cb[cm])*TILEB;
#pragma unroll
        for (int ks = 0; ks < 4; ks++){
            int k0 = ks*16;
            uint32_t a[4][4];
#pragma unroll
            for (int mi = 0; mi < 4; mi++)
                ldm_x4(a[mi], aT + (uint32_t)((wr*64 + mi*16 + arow)*144 + (k0 + akoff)*2));
            uint32_t b[2][4];
#pragma unroll
            for (int nj = 0; nj < 2; nj++)
                ldm_x4(b[nj], bT + (uint32_t)((wc*32 + nj*16 + bnode)*144 + (k0 + bkoff)*2));
#pragma unroll
            for (int mi = 0; mi < 4; mi++){
#pragma unroll
                for (int ni = 0; ni < 4; ni++){
                    uint32_t b0 = b[ni>>1][(ni&1)*2], b1 = b[ni>>1][(ni&1)*2 + 1];
                    mma_bf16(acc[mi][ni], a[mi], b0, b1);
                }
            }
        }
    }

    __syncthreads();   // operand tiles dead; reuse smem as the output stage

    // sigmoid -> stage [128][129]
    float* stg = (float*)smem;
    int gq = lid >> 2, tq = lid & 3;
#pragma unroll
    for (int mi = 0; mi < 4; mi++){
#pragma unroll
        for (int ni = 0; ni < 4; ni++){
            int r0 = wr*64 + mi*16 + gq;
            int c0 = wc*32 + ni*8 + tq*2;
            stg[r0*129 + c0]       = sigm(acc[mi][ni][0]);
            stg[r0*129 + c0 + 1]   = sigm(acc[mi][ni][1]);
            stg[(r0+8)*129 + c0]   = sigm(acc[mi][ni][2]);
            stg[(r0+8)*129 + c0+1] = sigm(acc[mi][ni][3]);
        }
    }
    __syncthreads();

    size_t gr0 = (size_t)by*128, gc0 = (size_t)bx*128;
    // direct store: row-major, coalesced
    for (int rr = wid; rr < 128; rr += 8){
        float* dst = out + O_ADJ + (gr0 + rr)*NNODE + gc0;
#pragma unroll
        for (int it = 0; it < 4; it++)
            dst[it*32 + lid] = stg[rr*129 + it*32 + lid];
    }
    // mirror store for off-diagonal tiles
    if (bx != by){
        for (int cc = wid; cc < 128; cc += 8){
            float* dst = out + O_ADJ + (gc0 + cc)*NNODE + gr0;
#pragma unroll
            for (int it = 0; it < 4; it++)
                dst[it*32 + lid] = stg[(it*32 + lid)*129 + cc];
        }
    }
}

// ---------------- host ----------------
extern "C" void kernel_launch(void* const* d_in, const int* in_sizes, int n_in,
                              void* d_out, int out_size)
{
    const float* feat = (const float*)d_in[0];
    const int*   esrc = (const int*)  d_in[1];
    const int*   edst = (const int*)  d_in[2];
    const float* ew   = (const float*)d_in[3];
    const float* aw   = (const float*)d_in[4];
    const int*   neg1 = (const int*)  d_in[5];
    const int*   neg2 = (const int*)  d_in[6];
    const int*   aidx = (const int*)  d_in[7];
    const int*   nidx = (const int*)  d_in[8];
    const float* alap = (const float*)d_in[9];
    const float* nlap = (const float*)d_in[10];
    const float* W1   = (const float*)d_in[11];
    const float* b1   = (const float*)d_in[12];
    const float* W2   = (const float*)d_in[13];
    const float* b2   = (const float*)d_in[14];
    const float* Wq   = (const float*)d_in[15];
    const float* bq   = (const float*)d_in[16];
    const float* Ws   = (const float*)d_in[17];
    const float* bs   = (const float*)d_in[18];
    const float* B1   = (const float*)d_in[19];
    const float* bd1  = (const float*)d_in[20];
    const float* B2   = (const float*)d_in[21];
    const float* bd2  = (const float*)d_in[22];
    const float* a1   = (const float*)d_in[23];
    const float* a2   = (const float*)d_in[24];
    const float* aq   = (const float*)d_in[25];
    float* out = (float*)d_out;

    float* fb = nullptr; int* ib = nullptr; __nv_bfloat16* spl = nullptr;
    cudaGetSymbolAddress((void**)&fb,  g_fbuf);
    cudaGetSymbolAddress((void**)&ib,  g_ibuf);
    cudaGetSymbolAddress((void**)&spl, g_split);
    float* h1    = fb + 0*NH;
    float* v1    = fb + 1*NH;
    float* h2    = fb + 2*NH;
    float* v2    = fb + 3*NH;
    float* nv    = fb + 4*NH;
    float* nbr   = fb + 6*NH;
    float* t1    = fb + 7*NH;
    float* t2    = fb + 8*NH;
    float* score = fb + 9*NH;
    int* cnt = ib;
    int* off = ib + NNODE;
    int* cur = ib + 2*NNODE;
    int* csr = ib + 3*NNODE;

    cudaFuncSetAttribute(k_adj_mma, cudaFuncAttributeMaxDynamicSharedMemorySize, SMA_SMEM);

    // CSR build + zero accumulators
    k_init<<<32, 256>>>(cnt, out);
    k_hist<<<NEDGE/256, 256>>>(edst, cnt);
    k_scan<<<1, 1024>>>(cnt, off, cur);
    k_scatter<<<NEDGE/256, 256>>>(edst, cur, csr);

    // GCN pipeline
    k_gemm64<<<128, 256>>>(feat, W1, nullptr, nullptr, h1);                      // node_transemb
    k_agg1<<<NNODE/4, 256>>>(esrc, ew, aw, off, cnt, csr, h1, b1, a1, v1, nbr);  // v1 + node_neighbor
    k_gemm64<<<128, 256>>>(v1, W2, nullptr, nullptr, h2);
    k_agg2<<<NNODE/4, 256>>>(esrc, ew, off, cnt, csr, h2, b2, a2, v2);
    k_gemm64<<<128, 256>>>(v2, Wq, bq, aq, nv);                                  // node_vec
    k_gemm64<<<128, 256>>>(feat, B1, nullptr, nullptr, t1);                      // feat@B1
    k_gemm64<<<128, 256>>>(nv, B2, nullptr, nullptr, t2);                        // nv@B2
    k_split<<<NH/256, 256>>>(nv, spl);                                           // bf16 hi/mid/lo

    // Discriminators + MIL scores
    k_disc<<<NNODE*32/256, 256>>>(t1, t2, nv, nbr, neg1, neg2, Ws, bs, bd1, bd2, score, out);

    // Subgraph losses
    k_subg<<<NSUB, 128>>>(aidx, nidx, alap, nlap, score, out);

    // adj_rebuilt via legacy tensor-core mma (dominant cost)
    k_adj_mma<<<ADJ_NT, 256, SMA_SMEM>>>(spl, out);

    (void)in_sizes; (void)n_in; (void)out_size;
}

// round 8
// speedup vs baseline: 1.2891x; 1.0698x over previous
#include <cuda_runtime.h>
#include <cuda_bf16.h>
#include <cstdint>

#define NNODE 8192
#define HDIM  64
#define NEDGE 262144
#define NSUB  128
#define KSUB  128
#define NNEG  4
#define NH    (NNODE*HDIM)

// output layout (tuple flattened in order)
#define O_ADJ ((size_t)4)
#define O_P1  ((size_t)4 + (size_t)NNODE*NNODE)
#define O_N1  (O_P1 + NNODE)
#define O_P2  (O_N1 + (size_t)NNEG*NNODE)
#define O_N2  (O_P2 + NNODE)

// scratch (no allocations allowed)
__device__ float          g_fbuf[9*NH + NNODE];
__device__ int            g_ibuf[3*NNODE + NEDGE];
__device__ __nv_bfloat16  g_split[3*NH];           // hi / mid / lo planes of node_vec

// ---------------- helpers ----------------
__device__ __forceinline__ float prelu_f(float x, float a){ return x >= 0.f ? x : a*x; }
__device__ __forceinline__ float sigm(float x){
    float e = __expf(-x);
    return __fdividef(1.f, 1.f + e);
}
__device__ __forceinline__ float warp_red(float v){
#pragma unroll
    for (int o = 16; o; o >>= 1) v += __shfl_xor_sync(0xffffffffu, v, o);
    return v;
}
__device__ __forceinline__ float blk_sum128(float v, float* red){
    int t = threadIdx.x;
    red[t] = v; __syncthreads();
#pragma unroll
    for (int o = 64; o > 0; o >>= 1){ if (t < o) red[t] += red[t + o]; __syncthreads(); }
    float r = red[0]; __syncthreads(); return r;
}
__device__ __forceinline__ float blk_max128(float v, float* red){
    int t = threadIdx.x;
    red[t] = v; __syncthreads();
#pragma unroll
    for (int o = 64; o > 0; o >>= 1){ if (t < o) red[t] = fmaxf(red[t], red[t + o]); __syncthreads(); }
    float r = red[0]; __syncthreads(); return r;
}
__device__ __forceinline__ uint32_t smem_u32(const void* p){
    uint32_t a;
    asm("{ .reg .u64 t; cvta.to.shared.u64 t, %1; cvt.u32.u64 %0, t; }" : "=r"(a) : "l"(p));
    return a;
}
__device__ __forceinline__ void ldm_x4(uint32_t* r, uint32_t addr){
    asm volatile("ldmatrix.sync.aligned.m8n8.x4.shared.b16 {%0,%1,%2,%3}, [%4];"
                 : "=r"(r[0]), "=r"(r[1]), "=r"(r[2]), "=r"(r[3]) : "r"(addr));
}
__device__ __forceinline__ void mma_bf16(float* c, const uint32_t* a, uint32_t b0, uint32_t b1){
    asm volatile(
        "mma.sync.aligned.m16n8k16.row.col.f32.bf16.bf16.f32 "
        "{%0,%1,%2,%3}, {%4,%5,%6,%7}, {%8,%9}, {%0,%1,%2,%3};"
        : "+f"(c[0]), "+f"(c[1]), "+f"(c[2]), "+f"(c[3])
        : "r"(a[0]), "r"(a[1]), "r"(a[2]), "r"(a[3]), "r"(b0), "r"(b1));
}

// ---------------- CSR build ----------------
__global__ void k_init(int* __restrict__ cnt, float* __restrict__ out){
    int i = blockIdx.x*blockDim.x + threadIdx.x;
    if (i < NNODE) cnt[i] = 0;
    if (i < 4) out[i] = 0.f;
}
// 8 edges/thread for MLP (latency-bound otherwise)
__global__ void __launch_bounds__(256) k_hist(const int* __restrict__ dst, int* __restrict__ cnt){
    int i = blockIdx.x*256 + threadIdx.x;
    int d[8];
#pragma unroll
    for (int j = 0; j < 8; j++) d[j] = dst[i + j*32768];
#pragma unroll
    for (int j = 0; j < 8; j++) atomicAdd(&cnt[d[j]], 1);
}
__global__ void __launch_bounds__(1024) k_scan(const int* __restrict__ cnt,
                                               int* __restrict__ off, int* __restrict__ cur){
    __shared__ int sh[1024];
    int t = threadIdx.x;
    int base = t*8;
    int loc[8]; int run = 0;
#pragma unroll
    for (int i = 0; i < 8; i++){ loc[i] = run; run += cnt[base + i]; }
    sh[t] = run; __syncthreads();
    for (int d = 1; d < 1024; d <<= 1){
        int v = 0; if (t >= d) v = sh[t - d];
        __syncthreads();
        sh[t] += v;
        __syncthreads();
    }
    int excl = sh[t] - run;
#pragma unroll
    for (int i = 0; i < 8; i++){ int o = excl + loc[i]; off[base+i] = o; cur[base+i] = o; }
}
__global__ void __launch_bounds__(256) k_scatter(const int* __restrict__ dst,
                                                 int* __restrict__ cur, int* __restrict__ csr){
    int i = blockIdx.x*256 + threadIdx.x;
    int d[8];
#pragma unroll
    for (int j = 0; j < 8; j++) d[j] = dst[i + j*32768];
#pragma unroll
    for (int j = 0; j < 8; j++){
        int p = atomicAdd(&cur[d[j]], 1);
        csr[p] = i + j*32768;
    }
}

// ---------------- dense [N,64]@[64,64] (+optional bias/prelu), 128 CTAs ----------------
__global__ void __launch_bounds__(256) k_gemm64(
    const float* __restrict__ X, const float* __restrict__ W,
    const float* __restrict__ bias, const float* __restrict__ slope,
    float* __restrict__ Y)
{
    __shared__ float4 Wsm[1024];
    __shared__ float  bsm[64];
    int t = threadIdx.x;
    const float4* W4 = (const float4*)W;
#pragma unroll
    for (int i = t; i < 1024; i += 256) Wsm[i] = W4[i];
    if (t < 64) bsm[t] = bias ? bias[t] : 0.f;
    __syncthreads();
    int row  = blockIdx.x*64 + (t & 63);
    int part = t >> 6;
    const float4* xr = (const float4*)(X + (size_t)row*64);
    float x[64];
#pragma unroll
    for (int i = 0; i < 16; i++){
        float4 v = xr[i];
        x[4*i]=v.x; x[4*i+1]=v.y; x[4*i+2]=v.z; x[4*i+3]=v.w;
    }
    bool act = (slope != nullptr);
    float sl = act ? *slope : 0.f;
    float4* yr = (float4*)(Y + (size_t)row*64);
#pragma unroll
    for (int cc = 0; cc < 4; cc++){
        int c4 = part*4 + cc;
        float4 acc = make_float4(0.f,0.f,0.f,0.f);
#pragma unroll
        for (int k = 0; k < 64; k++){
            float4 w = Wsm[k*16 + c4];
            acc.x = fmaf(x[k], w.x, acc.x);
            acc.y = fmaf(x[k], w.y, acc.y);
            acc.z = fmaf(x[k], w.z, acc.z);
            acc.w = fmaf(x[k], w.w, acc.w);
        }
        acc.x += bsm[4*c4]; acc.y += bsm[4*c4+1]; acc.z += bsm[4*c4+2]; acc.w += bsm[4*c4+3];
        if (act){
            acc.x = prelu_f(acc.x, sl); acc.y = prelu_f(acc.y, sl);
            acc.z = prelu_f(acc.z, sl); acc.w = prelu_f(acc.w, sl);
        }
        yr[c4] = acc;
    }
}

// ---------------- sparse aggregations (CSR gather, 64 threads/node) ----------------
__global__ void __launch_bounds__(256) k_agg1(
    const int* __restrict__ src, const float* __restrict__ ew, const float* __restrict__ aw,
    const int* __restrict__ off, const int* __restrict__ cnt, const int* __restrict__ csr,
    const float* __restrict__ h1, const float* __restrict__ b1, const float* __restrict__ a1p,
    float* __restrict__ v1, float* __restrict__ nbr)
{
    int t = threadIdx.x; int f = t & 63; int g = t >> 6;
    int n = blockIdx.x*4 + g;
    int o = off[n], c = cnt[n];
    float acc = 0.f, acc2 = 0.f;
    for (int i = 0; i < c; i++){
        int e = csr[o + i];
        int s = src[e];
        float v = h1[(size_t)s*64 + f];
        acc  = fmaf(ew[e], v, acc);
        acc2 = fmaf(aw[e], v, acc2);
    }
    float z = acc + b1[f];
    v1[(size_t)n*64 + f]  = prelu_f(z, *a1p);
    nbr[(size_t)n*64 + f] = acc2;
}
__global__ void __launch_bounds__(256) k_agg2(
    const int* __restrict__ src, const float* __restrict__ ew,
    const int* __restrict__ off, const int* __restrict__ cnt, const int* __restrict__ csr,
    const float* __restrict__ h2, const float* __restrict__ b2, const float* __restrict__ a2p,
    float* __restrict__ v2)
{
    int t = threadIdx.x; int f = t & 63; int g = t >> 6;
    int n = blockIdx.x*4 + g;
    int o = off[n], c = cnt[n];
    float acc = 0.f;
    for (int i = 0; i < c; i++){
        int e = csr[o + i];
        int s = src[e];
        acc = fmaf(ew[e], h2[(size_t)s*64 + f], acc);
    }
    float z = acc + b2[f];
    v2[(size_t)n*64 + f] = prelu_f(z, *a2p);
}

// ---------------- split nv into 3 bf16 planes (hi/mid/lo) ----------------
__global__ void k_split(const float* __restrict__ nv, __nv_bfloat16* __restrict__ sp){
    int i = blockIdx.x*256 + threadIdx.x;
    float a = nv[i];
    __nv_bfloat16 h = __float2bfloat16(a);
    float r1 = a - __bfloat162float(h);
    __nv_bfloat16 m = __float2bfloat16(r1);
    float r2 = r1 - __bfloat162float(m);
    __nv_bfloat16 l = __float2bfloat16(r2);
    sp[i] = h; sp[NH + i] = m; sp[2*NH + i] = l;
}

// ---------------- discriminators + score (1 warp / node) ----------------
__global__ void __launch_bounds__(256) k_disc(
    const float* __restrict__ t1, const float* __restrict__ t2,
    const float* __restrict__ nv, const float* __restrict__ nbr,
    const int* __restrict__ neg1, const int* __restrict__ neg2,
    const float* __restrict__ Ws, const float* __restrict__ bs,
    const float* __restrict__ bd1p, const float* __restrict__ bd2p,
    float* __restrict__ score, float* __restrict__ out)
{
    int tid = blockIdx.x*256 + threadIdx.x;
    int n = tid >> 5; int l = tid & 31;
    float nv0 = nv[(size_t)n*64 + l],  nv1 = nv[(size_t)n*64 + 32 + l];
    float nb0 = nbr[(size_t)n*64 + l], nb1 = nbr[(size_t)n*64 + 32 + l];
    float bd1 = *bd1p, bd2 = *bd2p;

    float d = warp_red(t1[(size_t)n*64 + l]*nv0 + t1[(size_t)n*64 + 32 + l]*nv1);
    if (l == 0) out[O_P1 + n] = d + bd1;
#pragma unroll
    for (int k = 0; k < NNEG; k++){
        int m = neg1[k*NNODE + n];
        float dk = warp_red(t1[(size_t)m*64 + l]*nv0 + t1[(size_t)m*64 + 32 + l]*nv1);
        if (l == 0) out[O_N1 + (size_t)k*NNODE + n] = dk + bd1;
    }
    float d2 = warp_red(t2[(size_t)n*64 + l]*nb0 + t2[(size_t)n*64 + 32 + l]*nb1);
    if (l == 0) out[O_P2 + n] = d2 + bd2;
#pragma unroll
    for (int k = 0; k < NNEG; k++){
        int m = neg2[k*NNODE + n];
        float dk = warp_red(t2[(size_t)m*64 + l]*nb0 + t2[(size_t)m*64 + 32 + l]*nb1);
        if (l == 0) out[O_N2 + (size_t)k*NNODE + n] = dk + bd2;
    }
    float sc = warp_red(Ws[l]*nv0 + Ws[32 + l]*nv1) + bs[0];
    if (l == 0) score[n] = sigm(sc);
}

// ---------------- subgraph losses ----------------
__global__ void __launch_bounds__(128) k_subg(
    const int* __restrict__ aidx, const int* __restrict__ nidx,
    const float* __restrict__ alap, const float* __restrict__ nlap,
    const float* __restrict__ score, float* __restrict__ out)
{
    __shared__ float sa[128], sn[128], red[128];
    int s = blockIdx.x, t = threadIdx.x;
    sa[t] = score[aidx[s*KSUB + t]];
    sn[t] = score[nidx[s*KSUB + t]];
    __syncthreads();
    const float* la = alap + ((size_t)s*KSUB + t)*KSUB;
    const float* ln = nlap + ((size_t)s*KSUB + t)*KSUB;
    float ra = 0.f, rn = 0.f;
#pragma unroll 4
    for (int j = 0; j < KSUB; j++){
        ra = fmaf(la[j], sa[j], ra);
        rn = fmaf(ln[j], sn[j], rn);
    }
    float myA = sa[t], myN = sn[t];
    float hc = myA*ra + myN*rn;

    float suma = blk_sum128(myA, red);
    float amax = blk_max128(myA, red);
    float nmax = blk_max128(myN, red);
    float mean = suma * (1.f/128.f);
    float bv = (myA < mean) ? myA : -1e30f;
    float below = blk_max128(bv, red);
    float abm = (below > -1e29f) ? below : amax;
    float hom = blk_sum128(hc, red);

    if (t == 0){
        atomicAdd(out + 0, fmaxf(0.f, 1.f - amax + nmax) * (1.f/128.f));
        atomicAdd(out + 1, fmaxf(0.f, 1.f - amax + abm)  * (1.f/128.f));
        atomicAdd(out + 2, suma * (1.f/128.f));
        atomicAdd(out + 3, hom  * (1.f/256.f));
    }
}

// ---------------- adj = sigmoid(nv @ nv^T) via mma.sync bf16, 3-way split, symmetric ----------------
#define ADJ_NT 2080
#define TPAD   72
#define TILEB  (128*TPAD*2)       // 18432 B
#define SMA_SMEM (6*TILEB)        // 110592 B; epilogue stage [128][129] f32 reuses this

__global__ void __launch_bounds__(256, 2) k_adj_mma(const __nv_bfloat16* __restrict__ sp,
                                                    float* __restrict__ out)
{
    extern __shared__ char smem[];
    uint32_t sb = smem_u32(smem);
    int t = threadIdx.x, wid = t >> 5, lid = t & 31;

    // triangular decode: i -> (by, bx) with bx <= by
    int i = blockIdx.x;
    int by = (int)((sqrtf(8.f*(float)i + 1.f) - 1.f) * 0.5f);
    while ((by+1)*(by+2)/2 <= i) by++;
    while (by*(by+1)/2 > i) by--;
    int bx = i - by*(by+1)/2;

    // load 6 operand tiles (A hi/mid/lo rows from by, B hi/mid/lo rows from bx)
    const uint4* g = (const uint4*)sp;          // per split: 65536 uint4; node row = 8 uint4
    for (int q = t; q < 6144; q += 256){
        int tile = q >> 10;
        int idx  = q & 1023;
        int r = idx >> 3, c = idx & 7;
        int s2   = (tile < 3) ? tile : tile - 3;
        int node = ((tile < 3) ? by : bx)*128 + r;
        uint4 v = g[s2*65536 + node*8 + c];
        *(uint4*)(smem + tile*TILEB + r*144 + c*16) = v;
    }
    __syncthreads();

    // warp tiling: 2 row-warps x 4 col-warps; each warp: 64 rows x 32 cols
    int wr = wid & 1, wc = wid >> 1;
    int arow  = lid & 15;
    int akoff = (lid >> 4) * 8;
    int bnode = (lid & 7) | ((lid >> 4) << 3);
    int bkoff = ((lid >> 3) & 1) * 8;

    float acc[4][4][4];
#pragma unroll
    for (int mi = 0; mi < 4; mi++)
#pragma unroll
        for (int ni = 0; ni < 4; ni++)
#pragma unroll
            for (int j = 0; j < 4; j++) acc[mi][ni][j] = 0.f;

    const int ca[6] = {0,0,1,0,2,1};
    const int cb[6] = {0,1,0,2,0,1};
#pragma unroll
    for (int cm = 0; cm < 6; cm++){
        uint32_t aT = sb + ca[cm]*TILEB;
        uint32_t bT = sb + (3 + cb[cm])*TILEB;
#pragma unroll
        for (int ks = 0; ks < 4; ks++){
            int k0 = ks*16;
            uint32_t a[4][4];
#pragma unroll
            for (int mi = 0; mi < 4; mi++)
                ldm_x4(a[mi], aT + (uint32_t)((wr*64 + mi*16 + arow)*144 + (k0 + akoff)*2));
            uint32_t b[2][4];
#pragma unroll
            for (int nj = 0; nj < 2; nj++)
                ldm_x4(b[nj], bT + (uint32_t)((wc*32 + nj*16 + bnode)*144 + (k0 + bkoff)*2));
#pragma unroll
            for (int mi = 0; mi < 4; mi++){
#pragma unroll
                for (int ni = 0; ni < 4; ni++){
                    uint32_t b0 = b[ni>>1][(ni&1)*2], b1 = b[ni>>1][(ni&1)*2 + 1];
                    mma_bf16(acc[mi][ni], a[mi], b0, b1);
                }
            }
        }
    }

    __syncthreads();   // operand tiles dead; reuse smem as the output stage

    // sigmoid -> stage [128][129]
    float* stg = (float*)smem;
    int gq = lid >> 2, tq = lid & 3;
#pragma unroll
    for (int mi = 0; mi < 4; mi++){
#pragma unroll
        for (int ni = 0; ni < 4; ni++){
            int r0 = wr*64 + mi*16 + gq;
            int c0 = wc*32 + ni*8 + tq*2;
            stg[r0*129 + c0]       = sigm(acc[mi][ni][0]);
            stg[r0*129 + c0 + 1]   = sigm(acc[mi][ni][1]);
            stg[(r0+8)*129 + c0]   = sigm(acc[mi][ni][2]);
            stg[(r0+8)*129 + c0+1] = sigm(acc[mi][ni][3]);
        }
    }
    __syncthreads();

    size_t gr0 = (size_t)by*128, gc0 = (size_t)bx*128;
    for (int rr = wid; rr < 128; rr += 8){
        float* dst = out + O_ADJ + (gr0 + rr)*NNODE + gc0;
#pragma unroll
        for (int it = 0; it < 4; it++)
            dst[it*32 + lid] = stg[rr*129 + it*32 + lid];
    }
    if (bx != by){
        for (int cc = wid; cc < 128; cc += 8){
            float* dst = out + O_ADJ + (gc0 + cc)*NNODE + gr0;
#pragma unroll
            for (int it = 0; it < 4; it++)
                dst[it*32 + lid] = stg[(it*32 + lid)*129 + cc];
        }
    }
}

// ---------------- host ----------------
extern "C" void kernel_launch(void* const* d_in, const int* in_sizes, int n_in,
                              void* d_out, int out_size)
{
    const float* feat = (const float*)d_in[0];
    const int*   esrc = (const int*)  d_in[1];
    const int*   edst = (const int*)  d_in[2];
    const float* ew   = (const float*)d_in[3];
    const float* aw   = (const float*)d_in[4];
    const int*   neg1 = (const int*)  d_in[5];
    const int*   neg2 = (const int*)  d_in[6];
    const int*   aidx = (const int*)  d_in[7];
    const int*   nidx = (const int*)  d_in[8];
    const float* alap = (const float*)d_in[9];
    const float* nlap = (const float*)d_in[10];
    const float* W1   = (const float*)d_in[11];
    const float* b1   = (const float*)d_in[12];
    const float* W2   = (const float*)d_in[13];
    const float* b2   = (const float*)d_in[14];
    const float* Wq   = (const float*)d_in[15];
    const float* bq   = (const float*)d_in[16];
    const float* Ws   = (const float*)d_in[17];
    const float* bs   = (const float*)d_in[18];
    const float* B1   = (const float*)d_in[19];
    const float* bd1  = (const float*)d_in[20];
    const float* B2   = (const float*)d_in[21];
    const float* bd2  = (const float*)d_in[22];
    const float* a1   = (const float*)d_in[23];
    const float* a2   = (const float*)d_in[24];
    const float* aq   = (const float*)d_in[25];
    float* out = (float*)d_out;

    float* fb = nullptr; int* ib = nullptr; __nv_bfloat16* spl = nullptr;
    cudaGetSymbolAddress((void**)&fb,  g_fbuf);
    cudaGetSymbolAddress((void**)&ib,  g_ibuf);
    cudaGetSymbolAddress((void**)&spl, g_split);
    float* h1    = fb + 0*NH;
    float* v1    = fb + 1*NH;
    float* h2    = fb + 2*NH;
    float* v2    = fb + 3*NH;
    float* nv    = fb + 4*NH;
    float* nbr   = fb + 6*NH;
    float* t1    = fb + 7*NH;
    float* t2    = fb + 8*NH;
    float* score = fb + 9*NH;
    int* cnt = ib;
    int* off = ib + NNODE;
    int* cur = ib + 2*NNODE;
    int* csr = ib + 3*NNODE;

    // one-time stream/event setup (host objects only; no device allocations)
    static cudaStream_t sA = nullptr, sB = nullptr;
    static cudaEvent_t eFork, eCSR, eT1, eNV, eAux;
    if (!sA){
        cudaStreamCreateWithFlags(&sA, cudaStreamNonBlocking);
        cudaStreamCreateWithFlags(&sB, cudaStreamNonBlocking);
        cudaEventCreateWithFlags(&eFork, cudaEventDisableTiming);
        cudaEventCreateWithFlags(&eCSR,  cudaEventDisableTiming);
        cudaEventCreateWithFlags(&eT1,   cudaEventDisableTiming);
        cudaEventCreateWithFlags(&eNV,   cudaEventDisableTiming);
        cudaEventCreateWithFlags(&eAux,  cudaEventDisableTiming);
        cudaFuncSetAttribute(k_adj_mma, cudaFuncAttributeMaxDynamicSharedMemorySize, SMA_SMEM);
    }

    // origin stream: zero counters/accumulators, then fork
    k_init<<<32, 256>>>(cnt, out);
    cudaEventRecord(eFork, 0);
    cudaStreamWaitEvent(sA, eFork, 0);
    cudaStreamWaitEvent(sB, eFork, 0);

    // sA: CSR build chain (independent of GEMMs)
    k_hist<<<128, 256, 0, sA>>>(edst, cnt);
    k_scan<<<1, 1024, 0, sA>>>(cnt, off, cur);
    k_scatter<<<128, 256, 0, sA>>>(edst, cur, csr);
    cudaEventRecord(eCSR, sA);

    // sB: feat @ B1 (independent)
    k_gemm64<<<128, 256, 0, sB>>>(feat, B1, nullptr, nullptr, t1);
    cudaEventRecord(eT1, sB);

    // origin: GCN chain
    k_gemm64<<<128, 256>>>(feat, W1, nullptr, nullptr, h1);                      // node_transemb
    cudaStreamWaitEvent(0, eCSR, 0);
    k_agg1<<<NNODE/4, 256>>>(esrc, ew, aw, off, cnt, csr, h1, b1, a1, v1, nbr);  // v1 + node_neighbor
    k_gemm64<<<128, 256>>>(v1, W2, nullptr, nullptr, h2);
    k_agg2<<<NNODE/4, 256>>>(esrc, ew, off, cnt, csr, h2, b2, a2, v2);
    k_gemm64<<<128, 256>>>(v2, Wq, bq, aq, nv);                                  // node_vec
    cudaEventRecord(eNV, 0);

    // sA: aux chain (t2 -> disc -> subg) runs concurrent with split+adj
    cudaStreamWaitEvent(sA, eNV, 0);
    cudaStreamWaitEvent(sA, eT1, 0);
    k_gemm64<<<128, 256, 0, sA>>>(nv, B2, nullptr, nullptr, t2);
    k_disc<<<NNODE*32/256, 256, 0, sA>>>(t1, t2, nv, nbr, neg1, neg2, Ws, bs, bd1, bd2, score, out);
    k_subg<<<NSUB, 128, 0, sA>>>(aidx, nidx, alap, nlap, score, out);
    cudaEventRecord(eAux, sA);

    // origin: split + adj (dominant cost)
    k_split<<<NH/256, 256>>>(nv, spl);
    k_adj_mma<<<ADJ_NT, 256, SMA_SMEM>>>(spl, out);
    cudaStreamWaitEvent(0, eAux, 0);   // join everything back to origin

    (void)in_sizes; (void)n_in; (void)out_size;
}

// round 12
// speedup vs baseline: 1.5922x; 1.2351x over previous
#include <cuda_runtime.h>
#include <cuda_fp16.h>
#include <cstdint>

#define NNODE 8192
#define HDIM  64
#define NEDGE 262144
#define NSUB  128
#define KSUB  128
#define NNEG  4
#define NH    (NNODE*HDIM)

// output layout (tuple flattened in order)
#define O_ADJ ((size_t)4)
#define O_P1  ((size_t)4 + (size_t)NNODE*NNODE)
#define O_N1  (O_P1 + NNODE)
#define O_P2  (O_N1 + (size_t)NNEG*NNODE)
#define O_N2  (O_P2 + NNODE)

// scratch (no allocations allowed)
__device__ float   g_fbuf[9*NH + NNODE];
__device__ int     g_ibuf[3*NNODE + NEDGE];
__device__ __half  g_split[2*NH];           // hi / mid fp16 planes of node_vec

// ---------------- helpers ----------------
__device__ __forceinline__ float prelu_f(float x, float a){ return x >= 0.f ? x : a*x; }
__device__ __forceinline__ float sigm(float x){
    float e = __expf(-x);
    return __fdividef(1.f, 1.f + e);
}
__device__ __forceinline__ float warp_red(float v){
#pragma unroll
    for (int o = 16; o; o >>= 1) v += __shfl_xor_sync(0xffffffffu, v, o);
    return v;
}
__device__ __forceinline__ float blk_sum128(float v, float* red){
    int t = threadIdx.x;
    red[t] = v; __syncthreads();
#pragma unroll
    for (int o = 64; o > 0; o >>= 1){ if (t < o) red[t] += red[t + o]; __syncthreads(); }
    float r = red[0]; __syncthreads(); return r;
}
__device__ __forceinline__ float blk_max128(float v, float* red){
    int t = threadIdx.x;
    red[t] = v; __syncthreads();
#pragma unroll
    for (int o = 64; o > 0; o >>= 1){ if (t < o) red[t] = fmaxf(red[t], red[t + o]); __syncthreads(); }
    float r = red[0]; __syncthreads(); return r;
}
__device__ __forceinline__ uint32_t smem_u32(const void* p){
    uint32_t a;
    asm("{ .reg .u64 t; cvta.to.shared.u64 t, %1; cvt.u32.u64 %0, t; }" : "=r"(a) : "l"(p));
    return a;
}
__device__ __forceinline__ void ldm_x4(uint32_t* r, uint32_t addr){
    asm volatile("ldmatrix.sync.aligned.m8n8.x4.shared.b16 {%0,%1,%2,%3}, [%4];"
                 : "=r"(r[0]), "=r"(r[1]), "=r"(r[2]), "=r"(r[3]) : "r"(addr));
}
__device__ __forceinline__ void mma_f16(float* c, const uint32_t* a, uint32_t b0, uint32_t b1){
    asm volatile(
        "mma.sync.aligned.m16n8k16.row.col.f32.f16.f16.f32 "
        "{%0,%1,%2,%3}, {%4,%5,%6,%7}, {%8,%9}, {%0,%1,%2,%3};"
        : "+f"(c[0]), "+f"(c[1]), "+f"(c[2]), "+f"(c[3])
        : "r"(a[0]), "r"(a[1]), "r"(a[2]), "r"(a[3]), "r"(b0), "r"(b1));
}

// ---------------- CSR build ----------------
__global__ void k_init(int* __restrict__ cnt, float* __restrict__ out){
    int i = blockIdx.x*blockDim.x + threadIdx.x;
    if (i < NNODE) cnt[i] = 0;
    if (i < 4) out[i] = 0.f;
}
__global__ void __launch_bounds__(256) k_hist(const int* __restrict__ dst, int* __restrict__ cnt){
    int i = blockIdx.x*256 + threadIdx.x;
    int d[8];
#pragma unroll
    for (int j = 0; j < 8; j++) d[j] = dst[i + j*32768];
#pragma unroll
    for (int j = 0; j < 8; j++) atomicAdd(&cnt[d[j]], 1);
}
__global__ void __launch_bounds__(1024) k_scan(const int* __restrict__ cnt,
                                               int* __restrict__ off, int* __restrict__ cur){
    __shared__ int sh[1024];
    int t = threadIdx.x;
    int base = t*8;
    int loc[8]; int run = 0;
#pragma unroll
    for (int i = 0; i < 8; i++){ loc[i] = run; run += cnt[base + i]; }
    sh[t] = run; __syncthreads();
    for (int d = 1; d < 1024; d <<= 1){
        int v = 0; if (t >= d) v = sh[t - d];
        __syncthreads();
        sh[t] += v;
        __syncthreads();
    }
    int excl = sh[t] - run;
#pragma unroll
    for (int i = 0; i < 8; i++){ int o = excl + loc[i]; off[base+i] = o; cur[base+i] = o; }
}
__global__ void __launch_bounds__(256) k_scatter(const int* __restrict__ dst,
                                                 int* __restrict__ cur, int* __restrict__ csr){
    int i = blockIdx.x*256 + threadIdx.x;
    int d[8];
#pragma unroll
    for (int j = 0; j < 8; j++) d[j] = dst[i + j*32768];
#pragma unroll
    for (int j = 0; j < 8; j++){
        int p = atomicAdd(&cur[d[j]], 1);
        csr[p] = i + j*32768;
    }
}

// ---------------- dense [N,64]@[64,64] (+optional bias/prelu), 128 CTAs ----------------
__global__ void __launch_bounds__(256) k_gemm64(
    const float* __restrict__ X, const float* __restrict__ W,
    const float* __restrict__ bias, const float* __restrict__ slope,
    float* __restrict__ Y)
{
    __shared__ float4 Wsm[1024];
    __shared__ float  bsm[64];
    int t = threadIdx.x;
    const float4* W4 = (const float4*)W;
#pragma unroll
    for (int i = t; i < 1024; i += 256) Wsm[i] = W4[i];
    if (t < 64) bsm[t] = bias ? bias[t] : 0.f;
    __syncthreads();
    int row  = blockIdx.x*64 + (t & 63);
    int part = t >> 6;
    const float4* xr = (const float4*)(X + (size_t)row*64);
    float x[64];
#pragma unroll
    for (int i = 0; i < 16; i++){
        float4 v = xr[i];
        x[4*i]=v.x; x[4*i+1]=v.y; x[4*i+2]=v.z; x[4*i+3]=v.w;
    }
    bool act = (slope != nullptr);
    float sl = act ? *slope : 0.f;
    float4* yr = (float4*)(Y + (size_t)row*64);
#pragma unroll
    for (int cc = 0; cc < 4; cc++){
        int c4 = part*4 + cc;
        float4 acc = make_float4(0.f,0.f,0.f,0.f);
#pragma unroll
        for (int k = 0; k < 64; k++){
            float4 w = Wsm[k*16 + c4];
            acc.x = fmaf(x[k], w.x, acc.x);
            acc.y = fmaf(x[k], w.y, acc.y);
            acc.z = fmaf(x[k], w.z, acc.z);
            acc.w = fmaf(x[k], w.w, acc.w);
        }
        acc.x += bsm[4*c4]; acc.y += bsm[4*c4+1]; acc.z += bsm[4*c4+2]; acc.w += bsm[4*c4+3];
        if (act){
            acc.x = prelu_f(acc.x, sl); acc.y = prelu_f(acc.y, sl);
            acc.z = prelu_f(acc.z, sl); acc.w = prelu_f(acc.w, sl);
        }
        yr[c4] = acc;
    }
}

// ---------------- sparse aggregations (CSR gather, 64 threads/node) ----------------
__global__ void __launch_bounds__(256) k_agg1(
    const int* __restrict__ src, const float* __restrict__ ew, const float* __restrict__ aw,
    const int* __restrict__ off, const int* __restrict__ cnt, const int* __restrict__ csr,
    const float* __restrict__ h1, const float* __restrict__ b1, const float* __restrict__ a1p,
    float* __restrict__ v1, float* __restrict__ nbr)
{
    int t = threadIdx.x; int f = t & 63; int g = t >> 6;
    int n = blockIdx.x*4 + g;
    int o = off[n], c = cnt[n];
    float acc = 0.f, acc2 = 0.f;
    for (int i = 0; i < c; i++){
        int e = csr[o + i];
        int s = src[e];
        float v = h1[(size_t)s*64 + f];
        acc  = fmaf(ew[e], v, acc);
        acc2 = fmaf(aw[e], v, acc2);
    }
    float z = acc + b1[f];
    v1[(size_t)n*64 + f]  = prelu_f(z, *a1p);
    nbr[(size_t)n*64 + f] = acc2;
}
__global__ void __launch_bounds__(256) k_agg2(
    const int* __restrict__ src, const float* __restrict__ ew,
    const int* __restrict__ off, const int* __restrict__ cnt, const int* __restrict__ csr,
    const float* __restrict__ h2, const float* __restrict__ b2, const float* __restrict__ a2p,
    float* __restrict__ v2)
{
    int t = threadIdx.x; int f = t & 63; int g = t >> 6;
    int n = blockIdx.x*4 + g;
    int o = off[n], c = cnt[n];
    float acc = 0.f;
    for (int i = 0; i < c; i++){
        int e = csr[o + i];
        int s = src[e];
        acc = fmaf(ew[e], h2[(size_t)s*64 + f], acc);
    }
    float z = acc + b2[f];
    v2[(size_t)n*64 + f] = prelu_f(z, *a2p);
}

// ---------------- split nv into 2 fp16 planes (hi/mid) ----------------
__global__ void k_split(const float* __restrict__ nv, __half* __restrict__ sp){
    int i = blockIdx.x*256 + threadIdx.x;
    float a = nv[i];
    __half h = __float2half_rn(a);
    float r1 = a - __half2float(h);
    __half m = __float2half_rn(r1);
    sp[i] = h; sp[NH + i] = m;
}

// ---------------- discriminators + score (1 warp / node) ----------------
__global__ void __launch_bounds__(256) k_disc(
    const float* __restrict__ t1, const float* __restrict__ t2,
    const float* __restrict__ nv, const float* __restrict__ nbr,
    const int* __restrict__ neg1, const int* __restrict__ neg2,
    const float* __restrict__ Ws, const float* __restrict__ bs,
    const float* __restrict__ bd1p, const float* __restrict__ bd2p,
    float* __restrict__ score, float* __restrict__ out)
{
    int tid = blockIdx.x*256 + threadIdx.x;
    int n = tid >> 5; int l = tid & 31;
    float nv0 = nv[(size_t)n*64 + l],  nv1 = nv[(size_t)n*64 + 32 + l];
    float nb0 = nbr[(size_t)n*64 + l], nb1 = nbr[(size_t)n*64 + 32 + l];
    float bd1 = *bd1p, bd2 = *bd2p;

    float d = warp_red(t1[(size_t)n*64 + l]*nv0 + t1[(size_t)n*64 + 32 + l]*nv1);
    if (l == 0) out[O_P1 + n] = d + bd1;
#pragma unroll
    for (int k = 0; k < NNEG; k++){
        int m = neg1[k*NNODE + n];
        float dk = warp_red(t1[(size_t)m*64 + l]*nv0 + t1[(size_t)m*64 + 32 + l]*nv1);
        if (l == 0) out[O_N1 + (size_t)k*NNODE + n] = dk + bd1;
    }
    float d2 = warp_red(t2[(size_t)n*64 + l]*nb0 + t2[(size_t)n*64 + 32 + l]*nb1);
    if (l == 0) out[O_P2 + n] = d2 + bd2;
#pragma unroll
    for (int k = 0; k < NNEG; k++){
        int m = neg2[k*NNODE + n];
        float dk = warp_red(t2[(size_t)m*64 + l]*nb0 + t2[(size_t)m*64 + 32 + l]*nb1);
        if (l == 0) out[O_N2 + (size_t)k*NNODE + n] = dk + bd2;
    }
    float sc = warp_red(Ws[l]*nv0 + Ws[32 + l]*nv1) + bs[0];
    if (l == 0) score[n] = sigm(sc);
}

// ---------------- subgraph losses ----------------
__global__ void __launch_bounds__(128) k_subg(
    const int* __restrict__ aidx, const int* __restrict__ nidx,
    const float* __restrict__ alap, const float* __restrict__ nlap,
    const float* __restrict__ score, float* __restrict__ out)
{
    __shared__ float sa[128], sn[128], red[128];
    int s = blockIdx.x, t = threadIdx.x;
    sa[t] = score[aidx[s*KSUB + t]];
    sn[t] = score[nidx[s*KSUB + t]];
    __syncthreads();
    const float* la = alap + ((size_t)s*KSUB + t)*KSUB;
    const float* ln = nlap + ((size_t)s*KSUB + t)*KSUB;
    float ra = 0.f, rn = 0.f;
#pragma unroll 4
    for (int j = 0; j < KSUB; j++){
        ra = fmaf(la[j], sa[j], ra);
        rn = fmaf(ln[j], sn[j], rn);
    }
    float myA = sa[t], myN = sn[t];
    float hc = myA*ra + myN*rn;

    float suma = blk_sum128(myA, red);
    float amax = blk_max128(myA, red);
    float nmax = blk_max128(myN, red);
    float mean = suma * (1.f/128.f);
    float bv = (myA < mean) ? myA : -1e30f;
    float below = blk_max128(bv, red);
    float abm = (below > -1e29f) ? below : amax;
    float hom = blk_sum128(hc, red);

    if (t == 0){
        atomicAdd(out + 0, fmaxf(0.f, 1.f - amax + nmax) * (1.f/128.f));
        atomicAdd(out + 1, fmaxf(0.f, 1.f - amax + abm)  * (1.f/128.f));
        atomicAdd(out + 2, suma * (1.f/128.f));
        atomicAdd(out + 3, hom  * (1.f/256.f));
    }
}

// ---------------- adj = sigmoid(nv @ nv^T) via mma.sync fp16, 2-way split, symmetric ----------------
// 2080 triangular 128x128 tiles. 3 combos (hh, hm, mh) cover 22 mantissa bits.
#define ADJ_NT 2080
#define TPAD   72
#define TILEB  (128*TPAD*2)       // 18432 B
#define SMA_SMEM (4*TILEB)        // 73728 B; epilogue stage [128][129] f32 (66048B) reuses this

__global__ void __launch_bounds__(256, 2) k_adj_mma(const __half* __restrict__ sp,
                                                    float* __restrict__ out)
{
    extern __shared__ char smem[];
    uint32_t sb = smem_u32(smem);
    int t = threadIdx.x, wid = t >> 5, lid = t & 31;

    // triangular decode: i -> (by, bx) with bx <= by
    int i = blockIdx.x;
    int by = (int)((sqrtf(8.f*(float)i + 1.f) - 1.f) * 0.5f);
    while ((by+1)*(by+2)/2 <= i) by++;
    while (by*(by+1)/2 > i) by--;
    int bx = i - by*(by+1)/2;

    // load 4 operand tiles: 0=A_h, 1=A_m (rows from by); 2=B_h, 3=B_m (rows from bx)
    const uint4* g = (const uint4*)sp;          // per plane: 65536 uint4; node row = 8 uint4
    for (int q = t; q < 4096; q += 256){
        int tile = q >> 10;
        int idx  = q & 1023;
        int r = idx >> 3, c = idx & 7;
        int plane = tile & 1;
        int node  = ((tile < 2) ? by : bx)*128 + r;
        uint4 v = g[plane*65536 + node*8 + c];
        *(uint4*)(smem + tile*TILEB + r*144 + c*16) = v;
    }
    __syncthreads();

    // warp tiling: 2 row-warps x 4 col-warps; each warp: 64 rows x 32 cols
    int wr = wid & 1, wc = wid >> 1;
    int arow  = lid & 15;
    int akoff = (lid >> 4) * 8;
    int bnode = (lid & 7) | ((lid >> 4) << 3);
    int bkoff = ((lid >> 3) & 1) * 8;

    float acc[4][4][4];
#pragma unroll
    for (int mi = 0; mi < 4; mi++)
#pragma unroll
        for (int ni = 0; ni < 4; ni++)
#pragma unroll
            for (int j = 0; j < 4; j++) acc[mi][ni][j] = 0.f;

    const int ca[3] = {0,0,1};   // A tile: h,h,m
    const int cb[3] = {2,3,2};   // B tile: h,m,h
#pragma unroll
    for (int cm = 0; cm < 3; cm++){
        uint32_t aT = sb + ca[cm]*TILEB;
        uint32_t bT = sb + cb[cm]*TILEB;
#pragma unroll
        for (int ks = 0; ks < 4; ks++){
            int k0 = ks*16;
            uint32_t a[4][4];
#pragma unroll
            for (int mi = 0; mi < 4; mi++)
                ldm_x4(a[mi], aT + (uint32_t)((wr*64 + mi*16 + arow)*144 + (k0 + akoff)*2));
            uint32_t b[2][4];
#pragma unroll
            for (int nj = 0; nj < 2; nj++)
                ldm_x4(b[nj], bT + (uint32_t)((wc*32 + nj*16 + bnode)*144 + (k0 + bkoff)*2));
#pragma unroll
            for (int mi = 0; mi < 4; mi++){
#pragma unroll
                for (int ni = 0; ni < 4; ni++){
                    uint32_t b0 = b[ni>>1][(ni&1)*2], b1 = b[ni>>1][(ni&1)*2 + 1];
                    mma_f16(acc[mi][ni], a[mi], b0, b1);
                }
            }
        }
    }

    __syncthreads();   // operand tiles dead; reuse smem as the output stage

    // sigmoid -> stage [128][129]
    float* stg = (float*)smem;
    int gq = lid >> 2, tq = lid & 3;
#pragma unroll
    for (int mi = 0; mi < 4; mi++){
#pragma unroll
        for (int ni = 0; ni < 4; ni++){
            int r0 = wr*64 + mi*16 + gq;
            int c0 = wc*32 + ni*8 + tq*2;
            stg[r0*129 + c0]       = sigm(acc[mi][ni][0]);
            stg[r0*129 + c0 + 1]   = sigm(acc[mi][ni][1]);
            stg[(r0+8)*129 + c0]   = sigm(acc[mi][ni][2]);
            stg[(r0+8)*129 + c0+1] = sigm(acc[mi][ni][3]);
        }
    }
    __syncthreads();

    size_t gr0 = (size_t)by*128, gc0 = (size_t)bx*128;
    for (int rr = wid; rr < 128; rr += 8){
        float* dst = out + O_ADJ + (gr0 + rr)*NNODE + gc0;
#pragma unroll
        for (int it = 0; it < 4; it++)
            dst[it*32 + lid] = stg[rr*129 + it*32 + lid];
    }
    if (bx != by){
        for (int cc = wid; cc < 128; cc += 8){
            float* dst = out + O_ADJ + (gc0 + cc)*NNODE + gr0;
#pragma unroll
            for (int it = 0; it < 4; it++)
                dst[it*32 + lid] = stg[(it*32 + lid)*129 + cc];
        }
    }
}

// ---------------- host ----------------
extern "C" void kernel_launch(void* const* d_in, const int* in_sizes, int n_in,
                              void* d_out, int out_size)
{
    const float* feat = (const float*)d_in[0];
    const int*   esrc = (const int*)  d_in[1];
    const int*   edst = (const int*)  d_in[2];
    const float* ew   = (const float*)d_in[3];
    const float* aw   = (const float*)d_in[4];
    const int*   neg1 = (const int*)  d_in[5];
    const int*   neg2 = (const int*)  d_in[6];
    const int*   aidx = (const int*)  d_in[7];
    const int*   nidx = (const int*)  d_in[8];
    const float* alap = (const float*)d_in[9];
    const float* nlap = (const float*)d_in[10];
    const float* W1   = (const float*)d_in[11];
    const float* b1   = (const float*)d_in[12];
    const float* W2   = (const float*)d_in[13];
    const float* b2   = (const float*)d_in[14];
    const float* Wq   = (const float*)d_in[15];
    const float* bq   = (const float*)d_in[16];
    const float* Ws   = (const float*)d_in[17];
    const float* bs   = (const float*)d_in[18];
    const float* B1   = (const float*)d_in[19];
    const float* bd1  = (const float*)d_in[20];
    const float* B2   = (const float*)d_in[21];
    const float* bd2  = (const float*)d_in[22];
    const float* a1   = (const float*)d_in[23];
    const float* a2   = (const float*)d_in[24];
    const float* aq   = (const float*)d_in[25];
    float* out = (float*)d_out;

    float* fb = nullptr; int* ib = nullptr; __half* spl = nullptr;
    cudaGetSymbolAddress((void**)&fb,  g_fbuf);
    cudaGetSymbolAddress((void**)&ib,  g_ibuf);
    cudaGetSymbolAddress((void**)&spl, g_split);
    float* h1    = fb + 0*NH;
    float* v1    = fb + 1*NH;
    float* h2    = fb + 2*NH;
    float* v2    = fb + 3*NH;
    float* nv    = fb + 4*NH;
    float* nbr   = fb + 6*NH;
    float* t1    = fb + 7*NH;
    float* t2    = fb + 8*NH;
    float* score = fb + 9*NH;
    int* cnt = ib;
    int* off = ib + NNODE;
    int* cur = ib + 2*NNODE;
    int* csr = ib + 3*NNODE;

    // one-time stream/event setup (host objects only; no device allocations)
    static cudaStream_t sA = nullptr, sB = nullptr;
    static cudaEvent_t eFork, eCSR, eT1, eNV, eAux;
    if (!sA){
        cudaStreamCreateWithFlags(&sA, cudaStreamNonBlocking);
        cudaStreamCreateWithFlags(&sB, cudaStreamNonBlocking);
        cudaEventCreateWithFlags(&eFork, cudaEventDisableTiming);
        cudaEventCreateWithFlags(&eCSR,  cudaEventDisableTiming);
        cudaEventCreateWithFlags(&eT1,   cudaEventDisableTiming);
        cudaEventCreateWithFlags(&eNV,   cudaEventDisableTiming);
        cudaEventCreateWithFlags(&eAux,  cudaEventDisableTiming);
        cudaFuncSetAttribute(k_adj_mma, cudaFuncAttributeMaxDynamicSharedMemorySize, SMA_SMEM);
    }

    // origin stream: zero counters/accumulators, then fork
    k_init<<<32, 256>>>(cnt, out);
    cudaEventRecord(eFork, 0);
    cudaStreamWaitEvent(sA, eFork, 0);
    cudaStreamWaitEvent(sB, eFork, 0);

    // sA: CSR build chain (independent of GEMMs)
    k_hist<<<128, 256, 0, sA>>>(edst, cnt);
    k_scan<<<1, 1024, 0, sA>>>(cnt, off, cur);
    k_scatter<<<128, 256, 0, sA>>>(edst, cur, csr);
    cudaEventRecord(eCSR, sA);

    // sB: feat @ B1 (independent)
    k_gemm64<<<128, 256, 0, sB>>>(feat, B1, nullptr, nullptr, t1);
    cudaEventRecord(eT1, sB);

    // origin: GCN chain
    k_gemm64<<<128, 256>>>(feat, W1, nullptr, nullptr, h1);                      // node_transemb
    cudaStreamWaitEvent(0, eCSR, 0);
    k_agg1<<<NNODE/4, 256>>>(esrc, ew, aw, off, cnt, csr, h1, b1, a1, v1, nbr);  // v1 + node_neighbor
    k_gemm64<<<128, 256>>>(v1, W2, nullptr, nullptr, h2);
    k_agg2<<<NNODE/4, 256>>>(esrc, ew, off, cnt, csr, h2, b2, a2, v2);
    k_gemm64<<<128, 256>>>(v2, Wq, bq, aq, nv);                                  // node_vec
    cudaEventRecord(eNV, 0);

    // sA: aux chain (t2 -> disc -> subg) runs concurrent with split+adj
    cudaStreamWaitEvent(sA, eNV, 0);
    cudaStreamWaitEvent(sA, eT1, 0);
    k_gemm64<<<128, 256, 0, sA>>>(nv, B2, nullptr, nullptr, t2);
    k_disc<<<NNODE*32/256, 256, 0, sA>>>(t1, t2, nv, nbr, neg1, neg2, Ws, bs, bd1, bd2, score, out);
    k_subg<<<NSUB, 128, 0, sA>>>(aidx, nidx, alap, nlap, score, out);
    cudaEventRecord(eAux, sA);

    // origin: split + adj (dominant cost)
    k_split<<<NH/256, 256>>>(nv, spl);
    k_adj_mma<<<ADJ_NT, 256, SMA_SMEM>>>(spl, out);
    cudaStreamWaitEvent(0, eAux, 0);   // join everything back to origin

    (void)in_sizes; (void)n_in; (void)out_size;
}